// round 16
// baseline (speedup 1.0000x reference)
#include <cuda_runtime.h>
#include <cstdint>

#define L2E  1.4426950408889634f
#define LN2f 0.6931471805599453f

constexpr int S = 256, W = 32, T = 32, RS = 36;
constexpr int DEP  = 16;         // eT ring depth (tiles)
constexpr int RAWB = 8;          // raw buffers per producer warp
constexpr int NPROD = 3;         // producer warps (1..3)

typedef unsigned long long u64;

__device__ float g_diff[64];
__device__ unsigned int g_ctr = 0;

static __device__ __forceinline__ float ex2f(float x){ float y; asm("ex2.approx.ftz.f32 %0, %1;" : "=f"(y) : "f"(x)); return y; }
static __device__ __forceinline__ float lg2f(float x){ float y; asm("lg2.approx.ftz.f32 %0, %1;" : "=f"(y) : "f"(x)); return y; }

static __device__ __forceinline__ u64 pack2(float lo, float hi){
    u64 r; asm("mov.b64 %0, {%1, %2};" : "=l"(r) : "f"(lo), "f"(hi)); return r;
}
static __device__ __forceinline__ void unpack2(u64 v, float& lo, float& hi){
    asm("mov.b64 {%0, %1}, %2;" : "=f"(lo), "=f"(hi) : "l"(v));
}
static __device__ __forceinline__ void fma2(u64& acc, u64 a, u64 b){
    asm("fma.rn.f32x2 %0, %1, %2, %0;" : "+l"(acc) : "l"(a), "l"(b));
}
static __device__ __forceinline__ void mul2(u64& d, u64 a, u64 b){
    asm("mul.rn.f32x2 %0, %1, %2;" : "=l"(d) : "l"(a), "l"(b));
}

__device__ __forceinline__ void cp_async16(uint32_t dst, const float* src){
    asm volatile("cp.async.cg.shared.global [%0], [%1], 16;\n" :: "r"(dst), "l"(src));
}
__device__ __forceinline__ void cp_commit(){ asm volatile("cp.async.commit_group;\n"); }
template<int N> __device__ __forceinline__ void cp_waitg(){ asm volatile("cp.async.wait_group %0;\n" :: "n"(N)); }

__device__ __forceinline__ int ld_acq(const int* p){
    int v;
    asm volatile("ld.acquire.cta.shared.b32 %0, [%1];"
                 : "=r"(v) : "r"((uint32_t)__cvta_generic_to_shared(p)) : "memory");
    return v;
}
__device__ __forceinline__ void st_rel(int* p, int v){
    asm volatile("st.release.cta.shared.b32 [%0], %1;"
                 :: "r"((uint32_t)__cvta_generic_to_shared(p)), "r"(v) : "memory");
}

__device__ __forceinline__ void bar2(){ asm volatile("bar.sync 2, 128;" ::: "memory"); }

extern __shared__ float dynsm[];   // [DEP][32*RS] eT ring, then [NPROD][RAWB][1024] raw

// One scan step; SL must be a compile-time constant after unrolling.
#define SCAN_STEP(SL, J)                                                      \
{                                                                             \
    const float* epf = eT + (((J) + 1) & (DEP - 1)) * (32 * RS) + lane * RS;  \
    const u64* ep = (const u64*)epf;                                          \
    u64 p0 = pack2(0.f, 0.f), p1 = pack2(0.f, 0.f);                           \
    _Pragma("unroll")                                                         \
    for (int m = 0; m < 8; m++) {                                             \
        const ulonglong2 e2v = *(const ulonglong2*)(ep + 2 * m);              \
        fma2(p0, e2v.x, R2[2 * m + 0]);                                       \
        fma2(p1, e2v.y, R2[2 * m + 1]);                                       \
    }                                                                         \
    float x0, x1, x2, x3;                                                     \
    unpack2(p0, x0, x1); unpack2(p1, x2, x3);                                 \
    const float partial = (x0 + x1) + (x2 + x3);                              \
    const float eTd = epf[(SL)];                                              \
    float D0 = 0.f, D1 = 0.f, D2 = 0.f, D3 = 0.f;                             \
    _Pragma("unroll")                                                         \
    for (int k = 0; k < 32; k += 4) {                                         \
        D0 = fmaf(__shfl_sync(~0u, w, k + 0), Ea[k + 0], D0);                 \
        D1 = fmaf(__shfl_sync(~0u, w, k + 1), Ea[k + 1], D1);                 \
        D2 = fmaf(__shfl_sync(~0u, w, k + 2), Ea[k + 2], D2);                 \
        D3 = fmaf(__shfl_sync(~0u, w, k + 3), Ea[k + 3], D3);                 \
    }                                                                         \
    const float Rn = (D0 + D1) + (D2 + D3);                                   \
    float rlo, rhi;                                                           \
    unpack2(R2[(SL) >> 1], rlo, rhi);                                         \
    const float Rold = ((SL) & 1) ? rhi : rlo;                                \
    R2[(SL) >> 1] = ((SL) & 1) ? pack2(rlo, Rn) : pack2(Rn, rhi);             \
    w = fmaf(eTd, Rn - Rold, partial);                                        \
}

// 4 fence-free steps behind one amortized acquire, rescale at group end.
#define SCAN_GROUP(JB, G)                                                     \
{                                                                             \
    const int t1 = (JB) + 4 * (G) + 1;                                        \
    for (;;) {                                                                \
        const int f0 = ld_acq(&sm_flag[(t1 + 0) & (DEP - 1)]);                \
        const int f1 = ld_acq(&sm_flag[(t1 + 1) & (DEP - 1)]);                \
        const int f2 = ld_acq(&sm_flag[(t1 + 2) & (DEP - 1)]);                \
        const int f3 = ld_acq(&sm_flag[(t1 + 3) & (DEP - 1)]);                \
        if ((f0 == t1) & (f1 == t1 + 1) & (f2 == t1 + 2) & (f3 == t1 + 3))    \
            break;                                                            \
    }                                                                         \
    SCAN_STEP(4 * (G) + 0, (JB) + 4 * (G) + 0);                               \
    {   float tmx = w;                                                        \
        _Pragma("unroll")                                                     \
        for (int o = 1; o < 32; o <<= 1)                                      \
            tmx = fmaxf(tmx, __shfl_xor_sync(0xffffffffu, tmx, o));           \
        wm_saved = tmx; }                                                     \
    SCAN_STEP(4 * (G) + 1, (JB) + 4 * (G) + 1);                               \
    SCAN_STEP(4 * (G) + 2, (JB) + 4 * (G) + 2);                               \
    SCAN_STEP(4 * (G) + 3, (JB) + 4 * (G) + 3);                               \
    {   const float delta = lg2f(wm_saved);                                   \
        const float f = ex2f(-delta);                                         \
        rho += delta;                                                         \
        const u64 ff = pack2(f, f);                                           \
        _Pragma("unroll")                                                     \
        for (int m = 0; m < 16; m++) mul2(R2[m], R2[m], ff);                  \
        w *= f; }                                                             \
    st_rel(&sm_prog, t1 + 4);                                                 \
}

__global__ __launch_bounds__(256, 1)
void crf_kernel(const float* __restrict__ logits,
                const int*   __restrict__ tags,
                const int*   __restrict__ mask,
                const float* __restrict__ trans,
                const float* __restrict__ start_tr,
                const float* __restrict__ end_tr,
                float* __restrict__ out)
{
    __shared__ float sm_trans[32 * 33];
    __shared__ int   sm_flag[DEP];
    __shared__ int   sm_prog;
    __shared__ int   sm_ired[8];
    __shared__ float sm_num[3];

    float* eT  = dynsm;
    float* raw = dynsm + DEP * 32 * RS;

    const int b    = blockIdx.x;
    const int tid  = threadIdx.x;
    const int warp = tid >> 5, lane = tid & 31;
    const float* lb = logits + (size_t)b * S * W * T;

    for (int i = tid; i < T * T; i += 256)
        sm_trans[(i >> 5) * 33 + (i & 31)] = trans[i];
    if (tid < DEP) sm_flag[tid] = -1;
    if (tid == 0)  sm_prog = 0;
    {
        int mv = mask[b * S + tid];
        #pragma unroll
        for (int o = 16; o; o >>= 1) mv += __shfl_xor_sync(~0u, mv, o);
        if (lane == 0) sm_ired[warp] = mv;
    }
    __syncthreads();
    int len = 0;
    #pragma unroll
    for (int i = 0; i < 8; i++) len += sm_ired[i];

    if (warp == 4) return;                 // SMSP0 exclusive to scanner

    // ================= numerator: warps 5,6,7 (concurrent) =================
    if (warp >= 5) {
        const int nw = warp - 5;
        const int* tb = tags + (size_t)b * S * W;
        float acc = 0.f;
        for (int p = nw; p < len - 1; p += 3) {
            const int ptg = __ldg(&tb[p * 32 + lane]);
            float V = 0.f;
            #pragma unroll
            for (int dd = 0; dd < 32; dd++) {
                const int pt = __shfl_sync(~0u, ptg, dd);
                if (pt != 0) V += sm_trans[pt * 33 + lane];
            }
            const int j  = p + 1 + lane;
            const int jv = (j < len) ? j : (len - 1);
            const int tg = __ldg(&tb[jv * 32 + lane]);
            const float vsel = __shfl_sync(~0u, V, tg);
            float e = 0.f;
            if (tg != 0) e = __ldg(&lb[(jv * 32 + lane) * 32 + tg]);
            if (j < len) acc += vsel + e;
        }
        if (nw == 0) {
            if (lane < len) {
                const int tgd = __ldg(&tb[lane * 33]);
                acc += __ldg(&start_tr[tgd]);
                if (tgd != 0) acc += __ldg(&lb[lane * 1056 + tgd]);
            }
            const int tgl = __ldg(&tb[(len - 1) * 32 + lane]);
            if (tgl != 0) acc += __ldg(&end_tr[tgl]);
        }
        #pragma unroll
        for (int o = 16; o; o >>= 1) acc += __shfl_xor_sync(~0u, acc, o);
        if (lane == 0) sm_num[nw] = acc;
        bar2();
        return;
    }

    // ================= producers: warps 1..3 (deep free-running) ===========
    if (warp != 0) {
        const int pw = warp - 1;                  // 0..2; owns tiles pw + 3k
        float* myraw = raw + pw * (RAWB * 1024);
        const uint32_t rawu = (uint32_t)__cvta_generic_to_shared(myraw);
        #pragma unroll
        for (int k = 0; k < RAWB; k++) {
            const int Jk = pw + NPROD * k;
            if (Jk < len) {
                const float* src = lb + (size_t)Jk * 1024;
                const uint32_t dst = rawu + (uint32_t)(k * 4096);
                #pragma unroll
                for (int c = 0; c < 8; c++)
                    cp_async16(dst + (uint32_t)((lane + 32 * c) * 16),
                               src + (lane + 32 * c) * 4);
            }
            cp_commit();
        }
        int k = 0;
        for (int J = pw; J < len; J += NPROD) {
            cp_waitg<RAWB - 1>();
            while (J >= ld_acq(&sm_prog) + DEP) ;
            const float* rb = myraw + k * 1024;
            float* dst = eT + (J & (DEP - 1)) * (32 * RS) + lane * RS;
            #pragma unroll
            for (int m = 0; m < 8; m++) {
                float4 v;
                v.x = ex2f(rb[(((J - 1 - (4 * m + 0)) & 31) << 5) + lane] * L2E);
                v.y = ex2f(rb[(((J - 1 - (4 * m + 1)) & 31) << 5) + lane] * L2E);
                v.z = ex2f(rb[(((J - 1 - (4 * m + 2)) & 31) << 5) + lane] * L2E);
                v.w = ex2f(rb[(((J - 1 - (4 * m + 3)) & 31) << 5) + lane] * L2E);
                *(float4*)(dst + 4 * m) = v;
            }
            st_rel(&sm_flag[J & (DEP - 1)], J);
            const int Jn = J + NPROD * RAWB;
            if (Jn < len) {
                const float* src = lb + (size_t)Jn * 1024;
                const uint32_t d2 = rawu + (uint32_t)(k * 4096);
                #pragma unroll
                for (int c = 0; c < 8; c++)
                    cp_async16(d2 + (uint32_t)((lane + 32 * c) * 16),
                               src + (lane + 32 * c) * 4);
            }
            cp_commit();
            k = (k + 1 == RAWB) ? 0 : k + 1;
        }
        return;
    }

    // ================= scanner: warp 0 =====================================
    float Ea[32];
    #pragma unroll
    for (int kk = 0; kk < 32; kk++)
        Ea[kk] = ex2f(sm_trans[kk * 33 + lane] * L2E);   // exp(trans[k][lane])
    const float end2 = end_tr[lane] * L2E;

    u64 R2[16];                                  // ring: slot sl -> R2[sl/2]
    #pragma unroll
    for (int m = 0; m < 15; m++) R2[m] = pack2(0.f, 0.f);
    R2[15] = pack2(0.f, ex2f(start_tr[lane] * L2E));   // slot 31 = start

    float rho = 0.f, w, wm_saved = 1.f;

    // ---- prologue: w_0 from tile 0 against init ring ----
    while (ld_acq(&sm_flag[0]) != 0) ;
    {
        const u64* ep = (const u64*)(eT + lane * RS);
        u64 p0 = pack2(0.f, 0.f), p1 = pack2(0.f, 0.f);
        #pragma unroll
        for (int m = 0; m < 8; m++) {
            const ulonglong2 e2v = *(const ulonglong2*)(ep + 2 * m);
            fma2(p0, e2v.x, R2[2 * m + 0]);
            fma2(p1, e2v.y, R2[2 * m + 1]);
        }
        float x0, x1, x2, x3;
        unpack2(p0, x0, x1); unpack2(p1, x2, x3);
        w = (x0 + x1) + (x2 + x3);
    }

    // ---- fast path: full 32-step blocks, fence amortized per 4 steps ----
    int jb = 0;
    for (; jb + 32 <= len - 1; jb += 32) {
        SCAN_GROUP(jb, 0); SCAN_GROUP(jb, 1);
        SCAN_GROUP(jb, 2); SCAN_GROUP(jb, 3);
        SCAN_GROUP(jb, 4); SCAN_GROUP(jb, 5);
        SCAN_GROUP(jb, 6); SCAN_GROUP(jb, 7);
    }

    // ---- tail: guarded per-step polls (static slots, <=31 steps) ----
    {
        #pragma unroll
        for (int sl = 0; sl < 32; sl++) {
            const int j = jb + sl;
            if (j < len - 1) {
                while (ld_acq(&sm_flag[(j + 1) & (DEP - 1)]) != j + 1) ;
                SCAN_STEP(sl, j);
                if ((sl & 3) == 1) {
                    float tmx = w;
                    #pragma unroll
                    for (int o = 1; o < 32; o <<= 1)
                        tmx = fmaxf(tmx, __shfl_xor_sync(0xffffffffu, tmx, o));
                    wm_saved = tmx;
                }
                if ((sl & 3) == 3) {
                    const float delta = lg2f(wm_saved);
                    const float f = ex2f(-delta);
                    rho += delta;
                    const u64 ff = pack2(f, f);
                    #pragma unroll
                    for (int m = 0; m < 16; m++) mul2(R2[m], R2[m], ff);
                    w *= f;
                    st_rel(&sm_prog, j + 2);
                }
            }
        }
    }

    // ---------------- finalize ----------------
    bar2();                                       // numerator partials ready
    const float v = rho + lg2f(w) + end2;         // alpha_{len-1}[t]*log2e + end
    float m = v;
    #pragma unroll
    for (int o = 1; o < 32; o <<= 1)
        m = fmaxf(m, __shfl_xor_sync(0xffffffffu, m, o));
    float s2 = ex2f(v - m);
    #pragma unroll
    for (int o = 1; o < 32; o <<= 1)
        s2 += __shfl_xor_sync(0xffffffffu, s2, o);

    const float num = sm_num[0] + sm_num[1] + sm_num[2];
    unsigned int done = 0;
    if (lane == 0) {
        const float den = LN2f * (m + lg2f(s2));
        out[1 + b] = num;
        g_diff[b]  = num - den;
        __threadfence();
        done = (atomicAdd(&g_ctr, 1u) == 63u) ? 1u : 0u;
    }
    done = __shfl_sync(~0u, done, 0);
    if (done) {
        float x = __ldcg(&g_diff[lane]) + __ldcg(&g_diff[lane + 32]);
        #pragma unroll
        for (int o = 16; o; o >>= 1) x += __shfl_xor_sync(~0u, x, o);
        if (lane == 0) {
            out[0] = x * (1.f / 64.f);
            g_ctr = 0;
        }
    }
}

extern "C" void kernel_launch(void* const* d_in, const int* in_sizes, int n_in,
                              void* d_out, int out_size)
{
    const float* logits = (const float*)d_in[0];
    const int*   tags   = (const int*)d_in[1];
    const int*   mask   = (const int*)d_in[2];
    const float* trans  = (const float*)d_in[3];
    const float* st     = (const float*)d_in[4];
    const float* en     = (const float*)d_in[5];
    float*       out    = (float*)d_out;

    const int dyn = (DEP * 32 * RS + NPROD * RAWB * 1024) * 4;   // 172032 B
    cudaFuncSetAttribute(crf_kernel, cudaFuncAttributeMaxDynamicSharedMemorySize, dyn);
    crf_kernel<<<64, 256, dyn>>>(logits, tags, mask, trans, st, en, out);
}

// round 17
// speedup vs baseline: 1.0213x; 1.0213x over previous
#include <cuda_runtime.h>
#include <cstdint>

#define L2E  1.4426950408889634f
#define LN2f 0.6931471805599453f

constexpr int S = 256, W = 32, T = 32, RS = 36;
constexpr int DEP  = 16;         // eT ring depth (tiles)
constexpr int RAWB = 8;          // raw buffers per producer warp
constexpr int NPROD = 3;         // producer warps (1..3)

typedef unsigned long long u64;

__device__ float g_diff[64];
__device__ unsigned int g_ctr = 0;

static __device__ __forceinline__ float ex2f(float x){ float y; asm("ex2.approx.ftz.f32 %0, %1;" : "=f"(y) : "f"(x)); return y; }
static __device__ __forceinline__ float lg2f(float x){ float y; asm("lg2.approx.ftz.f32 %0, %1;" : "=f"(y) : "f"(x)); return y; }

static __device__ __forceinline__ u64 pack2(float lo, float hi){
    u64 r; asm("mov.b64 %0, {%1, %2};" : "=l"(r) : "f"(lo), "f"(hi)); return r;
}
static __device__ __forceinline__ void unpack2(u64 v, float& lo, float& hi){
    asm("mov.b64 {%0, %1}, %2;" : "=f"(lo), "=f"(hi) : "l"(v));
}
static __device__ __forceinline__ void fma2(u64& acc, u64 a, u64 b){
    asm("fma.rn.f32x2 %0, %1, %2, %0;" : "+l"(acc) : "l"(a), "l"(b));
}
static __device__ __forceinline__ void mul2(u64& d, u64 a, u64 b){
    asm("mul.rn.f32x2 %0, %1, %2;" : "=l"(d) : "l"(a), "l"(b));
}

__device__ __forceinline__ int ld_acq(const int* p){
    int v;
    asm volatile("ld.acquire.cta.shared.b32 %0, [%1];"
                 : "=r"(v) : "r"((uint32_t)__cvta_generic_to_shared(p)) : "memory");
    return v;
}
__device__ __forceinline__ void st_rel(int* p, int v){
    asm volatile("st.release.cta.shared.b32 [%0], %1;"
                 :: "r"((uint32_t)__cvta_generic_to_shared(p)), "r"(v) : "memory");
}

__device__ __forceinline__ void mbar_init(uint32_t mbar, uint32_t cnt){
    asm volatile("mbarrier.init.shared.b64 [%0], %1;" :: "r"(mbar), "r"(cnt) : "memory");
}
__device__ __forceinline__ void mbar_expect_tx(uint32_t mbar, uint32_t bytes){
    asm volatile("mbarrier.arrive.expect_tx.shared.b64 _, [%0], %1;"
                 :: "r"(mbar), "r"(bytes) : "memory");
}
__device__ __forceinline__ void bulk_g2s(uint32_t dst, const void* src, uint32_t bytes, uint32_t mbar){
    asm volatile("cp.async.bulk.shared::cta.global.mbarrier::complete_tx::bytes [%0], [%1], %2, [%3];"
                 :: "r"(dst), "l"(src), "r"(bytes), "r"(mbar) : "memory");
}
__device__ __forceinline__ void mbar_wait(uint32_t mbar, uint32_t parity){
    asm volatile(
        "{\n\t"
        ".reg .pred P1;\n\t"
        "WAIT_LOOP_%=:\n\t"
        "mbarrier.try_wait.parity.acquire.cta.shared::cta.b64 P1, [%0], %1, 0x989680;\n\t"
        "@P1 bra.uni WAIT_DONE_%=;\n\t"
        "bra.uni WAIT_LOOP_%=;\n\t"
        "WAIT_DONE_%=:\n\t"
        "}"
        :: "r"(mbar), "r"(parity) : "memory");
}
__device__ __forceinline__ void fence_async_shared(){
    asm volatile("fence.proxy.async.shared::cta;" ::: "memory");
}

__device__ __forceinline__ void bar2(){ asm volatile("bar.sync 2, 128;" ::: "memory"); }

extern __shared__ float dynsm[];   // [DEP][32*RS] eT ring, then [NPROD][RAWB][1024] raw

__global__ __launch_bounds__(256, 1)
void crf_kernel(const float* __restrict__ logits,
                const int*   __restrict__ tags,
                const int*   __restrict__ mask,
                const float* __restrict__ trans,
                const float* __restrict__ start_tr,
                const float* __restrict__ end_tr,
                float* __restrict__ out)
{
    __shared__ float sm_trans[32 * 33];
    __shared__ __align__(16) float sm_w[32];
    __shared__ __align__(8) u64 sm_mbar[NPROD][RAWB];
    __shared__ int   sm_flag[DEP];
    __shared__ int   sm_prog;
    __shared__ int   sm_ired[8];
    __shared__ float sm_num[3];

    float* eT  = dynsm;
    float* raw = dynsm + DEP * 32 * RS;

    const int b    = blockIdx.x;
    const int tid  = threadIdx.x;
    const int warp = tid >> 5, lane = tid & 31;
    const float* lb = logits + (size_t)b * S * W * T;

    for (int i = tid; i < T * T; i += 256)
        sm_trans[(i >> 5) * 33 + (i & 31)] = trans[i];
    if (tid < DEP) sm_flag[tid] = -1;
    if (tid == 0)  sm_prog = 0;
    {
        int mv = mask[b * S + tid];
        #pragma unroll
        for (int o = 16; o; o >>= 1) mv += __shfl_xor_sync(~0u, mv, o);
        if (lane == 0) sm_ired[warp] = mv;
    }
    __syncthreads();
    int len = 0;
    #pragma unroll
    for (int i = 0; i < 8; i++) len += sm_ired[i];

    if (warp == 4) return;                 // SMSP0 exclusive to scanner

    // ================= numerator: warps 5,6,7 (concurrent) =================
    if (warp >= 5) {
        const int nw = warp - 5;
        const int* tb = tags + (size_t)b * S * W;
        float acc = 0.f;
        for (int p = nw; p < len - 1; p += 3) {
            const int ptg = __ldg(&tb[p * 32 + lane]);
            float V = 0.f;
            #pragma unroll
            for (int dd = 0; dd < 32; dd++) {
                const int pt = __shfl_sync(~0u, ptg, dd);
                if (pt != 0) V += sm_trans[pt * 33 + lane];
            }
            const int j  = p + 1 + lane;
            const int jv = (j < len) ? j : (len - 1);
            const int tg = __ldg(&tb[jv * 32 + lane]);
            const float vsel = __shfl_sync(~0u, V, tg);
            float e = 0.f;
            if (tg != 0) e = __ldg(&lb[(jv * 32 + lane) * 32 + tg]);
            if (j < len) acc += vsel + e;
        }
        if (nw == 0) {
            if (lane < len) {
                const int tgd = __ldg(&tb[lane * 33]);
                acc += __ldg(&start_tr[tgd]);
                if (tgd != 0) acc += __ldg(&lb[lane * 1056 + tgd]);
            }
            const int tgl = __ldg(&tb[(len - 1) * 32 + lane]);
            if (tgl != 0) acc += __ldg(&end_tr[tgl]);
        }
        #pragma unroll
        for (int o = 16; o; o >>= 1) acc += __shfl_xor_sync(~0u, acc, o);
        if (lane == 0) sm_num[nw] = acc;
        bar2();
        return;
    }

    // ====== producers: warps 1..3 — bulk-copy feed + convert ===============
    if (warp != 0) {
        const int pw = warp - 1;                  // 0..2; owns tiles pw + 3k
        float* myraw = raw + pw * (RAWB * 1024);
        const uint32_t rawu = (uint32_t)__cvta_generic_to_shared(myraw);
        const uint32_t mb0  = (uint32_t)__cvta_generic_to_shared(&sm_mbar[pw][0]);

        if (lane == 0) {
            #pragma unroll
            for (int k = 0; k < RAWB; k++) mbar_init(mb0 + 8u * k, 1);
            fence_async_shared();
        }
        __syncwarp();
        if (lane == 0) {
            #pragma unroll
            for (int k = 0; k < RAWB; k++) {      // prologue: RAWB bulk loads
                const int Jk = pw + NPROD * k;
                if (Jk < len) {
                    mbar_expect_tx(mb0 + 8u * k, 4096u);
                    bulk_g2s(rawu + (uint32_t)(k * 4096), lb + (size_t)Jk * 1024,
                             4096u, mb0 + 8u * k);
                }
            }
        }
        __syncwarp();

        unsigned ph = 0;                          // per-buffer phase bits
        int k = 0;
        for (int J = pw; J < len; J += NPROD) {
            while (J >= ld_acq(&sm_prog) + DEP) ; // eT ring backpressure
            mbar_wait(mb0 + 8u * k, (ph >> k) & 1u);
            ph ^= 1u << k;
            const float* rb = myraw + k * 1024;
            float* dst = eT + (J & (DEP - 1)) * (32 * RS) + lane * RS;
            #pragma unroll
            for (int m = 0; m < 8; m++) {
                float4 v;
                v.x = ex2f(rb[(((J - 1 - (4 * m + 0)) & 31) << 5) + lane] * L2E);
                v.y = ex2f(rb[(((J - 1 - (4 * m + 1)) & 31) << 5) + lane] * L2E);
                v.z = ex2f(rb[(((J - 1 - (4 * m + 2)) & 31) << 5) + lane] * L2E);
                v.w = ex2f(rb[(((J - 1 - (4 * m + 3)) & 31) << 5) + lane] * L2E);
                *(float4*)(dst + 4 * m) = v;
            }
            st_rel(&sm_flag[J & (DEP - 1)], J);
            __syncwarp();                         // all lanes done reading buf k
            const int Jn = J + NPROD * RAWB;      // refill freed buffer
            if (lane == 0 && Jn < len) {
                mbar_expect_tx(mb0 + 8u * k, 4096u);
                bulk_g2s(rawu + (uint32_t)(k * 4096), lb + (size_t)Jn * 1024,
                         4096u, mb0 + 8u * k);
            }
            k = (k + 1 == RAWB) ? 0 : k + 1;
        }
        return;
    }

    // ================= scanner: warp 0 (R15-proven form) ===================
    u64 E2[16];
    {
        float Ea[32];
        #pragma unroll
        for (int kk = 0; kk < 32; kk++)
            Ea[kk] = ex2f(sm_trans[kk * 33 + lane] * L2E);
        #pragma unroll
        for (int m = 0; m < 16; m++) E2[m] = pack2(Ea[2 * m], Ea[2 * m + 1]);
    }
    const float end2 = end_tr[lane] * L2E;

    u64 R2[16];                                  // ring: slot sl -> R2[sl/2]
    #pragma unroll
    for (int m = 0; m < 15; m++) R2[m] = pack2(0.f, 0.f);
    R2[15] = pack2(0.f, ex2f(start_tr[lane] * L2E));   // slot 31 = start

    float rho = 0.f, w, wm_saved = 1.f;

    // ---- prologue: w_0 from tile 0 against init ring ----
    while (ld_acq(&sm_flag[0]) != 0) ;
    {
        const u64* ep = (const u64*)(eT + lane * RS);
        u64 p0 = pack2(0.f, 0.f), p1 = pack2(0.f, 0.f);
        #pragma unroll
        for (int m = 0; m < 8; m++) {
            const ulonglong2 e2v = *(const ulonglong2*)(ep + 2 * m);
            fma2(p0, e2v.x, R2[2 * m + 0]);
            fma2(p1, e2v.y, R2[2 * m + 1]);
        }
        float x0, x1, x2, x3;
        unpack2(p0, x0, x1); unpack2(p1, x2, x3);
        w = (x0 + x1) + (x2 + x3);
    }

    // ---- main loop: iteration j computes Rn_j (stage2) and w_{j+1} ----
    for (int jb = 0; jb < len - 1; jb += 32) {
        #pragma unroll
        for (int sl = 0; sl < 32; sl++) {
            const int j = jb + sl;
            if (j < len - 1) {
                sm_w[lane] = w;                   // broadcast w_j (chain head)
                __syncwarp();
                while (ld_acq(&sm_flag[(j + 1) & (DEP - 1)]) != j + 1) ;
                const float* epf = eT + ((j + 1) & (DEP - 1)) * (32 * RS) + lane * RS;
                const u64*   ep  = (const u64*)epf;
                u64 p0 = pack2(0.f, 0.f), p1 = pack2(0.f, 0.f);
                #pragma unroll
                for (int m = 0; m < 8; m++) {
                    const ulonglong2 e2v = *(const ulonglong2*)(ep + 2 * m);
                    fma2(p0, e2v.x, R2[2 * m + 0]);
                    fma2(p1, e2v.y, R2[2 * m + 1]);
                }
                float x0, x1, x2, x3;
                unpack2(p0, x0, x1); unpack2(p1, x2, x3);
                const float partial = (x0 + x1) + (x2 + x3);
                const float eTd = epf[sl];        // eT_{j+1}[t][sl_j]
                u64 d0 = pack2(0.f, 0.f), d1 = pack2(0.f, 0.f);
                #pragma unroll
                for (int m = 0; m < 8; m++) {
                    const ulonglong2 w2 = *(const ulonglong2*)(sm_w + 4 * m);
                    fma2(d0, w2.x, E2[2 * m + 0]);
                    fma2(d1, w2.y, E2[2 * m + 1]);
                }
                float y0, y1, y2, y3;
                unpack2(d0, y0, y1); unpack2(d1, y2, y3);
                const float Rn = (y0 + y1) + (y2 + y3);
                float lo, hi;
                unpack2(R2[sl >> 1], lo, hi);
                const float Rold = (sl & 1) ? hi : lo;
                R2[sl >> 1] = (sl & 1) ? pack2(lo, Rn) : pack2(Rn, hi);
                w = fmaf(eTd, Rn - Rold, partial);
                if ((sl & 3) == 1) {              // stale max (off-chain)
                    float t = w;
                    #pragma unroll
                    for (int o = 1; o < 32; o <<= 1)
                        t = fmaxf(t, __shfl_xor_sync(0xffffffffu, t, o));
                    wm_saved = t;
                }
                if ((sl & 3) == 3) {              // epoch rescale + publish
                    const float delta = lg2f(wm_saved);
                    const float f = ex2f(-delta);
                    rho += delta;
                    const u64 ff = pack2(f, f);
                    #pragma unroll
                    for (int m = 0; m < 16; m++) mul2(R2[m], R2[m], ff);
                    w *= f;
                    st_rel(&sm_prog, j + 2);
                }
            }
        }
    }

    // ---------------- finalize ----------------
    bar2();                                       // numerator partials ready
    const float v = rho + lg2f(w) + end2;
    float m = v;
    #pragma unroll
    for (int o = 1; o < 32; o <<= 1)
        m = fmaxf(m, __shfl_xor_sync(0xffffffffu, m, o));
    float s2 = ex2f(v - m);
    #pragma unroll
    for (int o = 1; o < 32; o <<= 1)
        s2 += __shfl_xor_sync(0xffffffffu, s2, o);

    const float num = sm_num[0] + sm_num[1] + sm_num[2];
    unsigned int done = 0;
    if (lane == 0) {
        const float den = LN2f * (m + lg2f(s2));
        out[1 + b] = num;
        g_diff[b]  = num - den;
        __threadfence();
        done = (atomicAdd(&g_ctr, 1u) == 63u) ? 1u : 0u;
    }
    done = __shfl_sync(~0u, done, 0);
    if (done) {
        float x = __ldcg(&g_diff[lane]) + __ldcg(&g_diff[lane + 32]);
        #pragma unroll
        for (int o = 16; o; o >>= 1) x += __shfl_xor_sync(~0u, x, o);
        if (lane == 0) {
            out[0] = x * (1.f / 64.f);
            g_ctr = 0;
        }
    }
}

extern "C" void kernel_launch(void* const* d_in, const int* in_sizes, int n_in,
                              void* d_out, int out_size)
{
    const float* logits = (const float*)d_in[0];
    const int*   tags   = (const int*)d_in[1];
    const int*   mask   = (const int*)d_in[2];
    const float* trans  = (const float*)d_in[3];
    const float* st     = (const float*)d_in[4];
    const float* en     = (const float*)d_in[5];
    float*       out    = (float*)d_out;

    const int dyn = (DEP * 32 * RS + NPROD * RAWB * 1024) * 4;   // 172032 B
    cudaFuncSetAttribute(crf_kernel, cudaFuncAttributeMaxDynamicSharedMemorySize, dyn);
    crf_kernel<<<64, 256, dyn>>>(logits, tags, mask, trans, st, en, out);
}